// round 11
// baseline (speedup 1.0000x reference)
#include <cuda_runtime.h>
#include <cstdint>
#include <cstddef>

// Problem constants
#define BATCH  4
#define NSEQ   2048
#define DMODEL 1024
#define NHEAD  16
#define DKH    64
#define MROWS  (BATCH * NSEQ)   // 8192
#define NEGVAL (-1e11f)

// ---------------- scratch (device globals; no allocation allowed) ----------
__device__ float    g_Q[BATCH * NHEAD * NSEQ * DKH];   // (B,H,N,DK)
__device__ float    g_K[BATCH * NHEAD * NSEQ * DKH];
__device__ float    g_V[BATCH * NHEAD * NSEQ * DKH];
__device__ float    g_C[BATCH * NSEQ * DMODEL];        // attention context (B,N,D)
__device__ unsigned g_pmask[BATCH * NSEQ * NSEQ / 32]; // bit-packed mask

// ---------------- helpers ---------------------------------------------------
__device__ __forceinline__ uint32_t f2tf32(float x) {
    uint32_t r;
    asm("cvt.rna.tf32.f32 %0, %1;" : "=r"(r) : "f"(x));
    return r;
}

__device__ __forceinline__ void mma_tf32(float* c, const uint32_t* a,
                                         uint32_t b0, uint32_t b1) {
    asm volatile(
        "mma.sync.aligned.m16n8k8.row.col.f32.tf32.tf32.f32 "
        "{%0,%1,%2,%3}, {%4,%5,%6,%7}, {%8,%9}, {%0,%1,%2,%3};"
        : "+f"(c[0]), "+f"(c[1]), "+f"(c[2]), "+f"(c[3])
        : "r"(a[0]), "r"(a[1]), "r"(a[2]), "r"(a[3]), "r"(b0), "r"(b1));
}

__device__ __forceinline__ void mma_bf16(float* c, const uint32_t* a,
                                         uint32_t b0, uint32_t b1) {
    asm volatile(
        "mma.sync.aligned.m16n8k16.row.col.f32.bf16.bf16.f32 "
        "{%0,%1,%2,%3}, {%4,%5,%6,%7}, {%8,%9}, {%0,%1,%2,%3};"
        : "+f"(c[0]), "+f"(c[1]), "+f"(c[2]), "+f"(c[3])
        : "r"(a[0]), "r"(a[1]), "r"(a[2]), "r"(a[3]), "r"(b0), "r"(b1));
}

// pack two floats to bf16x2: lo_val -> low half (lower k), hi_val -> high half
__device__ __forceinline__ uint32_t pack_bf16x2(float lo_val, float hi_val) {
    uint32_t r;
    asm("cvt.rn.bf16x2.f32 %0, %1, %2;" : "=r"(r) : "f"(hi_val), "f"(lo_val));
    return r;
}

__device__ __forceinline__ void cp16(uint32_t dst, const float* src) {
    asm volatile("cp.async.ca.shared.global [%0], [%1], 16;\n"
                 :: "r"(dst), "l"(src));
}
__device__ __forceinline__ void cp_commit() {
    asm volatile("cp.async.commit_group;\n");
}
template <int N>
__device__ __forceinline__ void cp_wait() {
    asm volatile("cp.async.wait_group %0;\n" :: "n"(N));
}

// ---------------- mask bit-pack: 67MB int32 -> 2MB bits --------------------
__global__ void pack_mask_kernel(const int* __restrict__ mask) {
    int idx = blockIdx.x * blockDim.x + threadIdx.x;
    unsigned bit = (mask[idx] != 0) ? 1u : 0u;
    unsigned w = __ballot_sync(0xffffffffu, bit);
    if ((threadIdx.x & 31) == 0) g_pmask[idx >> 5] = w;
}

// ---------------- projection GEMM core: 3xBF16 + cp.async pipeline ----------
// C(8192x1024) = A @ W + bias.  Block tile 128x128, BK=16, 256 threads (8 warps,
// 2x4 warp grid, warp tile 64x32).  Raw fp32 staged via cp.async (double-
// buffered); per-tile pre-split pass packs bf16x2 hi/lo arrays; mma loop is
// pure LDS + mma.m16n8k16.bf16, 3 terms (ahbh + ahbl + albh), err ~1e-5.
#define AST 20    // raw A row stride (floats), 16B-aligned chunks
#define BST 136   // raw B row stride (floats)
#define PKS 136   // packed array row stride (u32): banks lk*8+lg all distinct
// dynamic smem: rawA 2*128*AST + rawB 2*16*BST floats, 4 packed 8*PKS u32 arrays
#define PROJ_SMEM ((2 * 128 * AST + 2 * 16 * BST + 4 * 8 * PKS) * 4)

template <bool SPLIT>
__device__ __forceinline__ void proj_core(const float* __restrict__ A,
                                          const float* __restrict__ W,
                                          const float* __restrict__ bias,
                                          float* __restrict__ out) {
    extern __shared__ char psm[];
    float*    rA = (float*)psm;                       // [2][128*AST]
    float*    rB = rA + 2 * 128 * AST;                // [2][16*BST]
    uint32_t* AH = (uint32_t*)(rB + 2 * 16 * BST);    // [8][PKS] bf16x2 k-pairs
    uint32_t* AL = AH + 8 * PKS;
    uint32_t* BH = AL + 8 * PKS;
    uint32_t* BL = BH + 8 * PKS;

    const int tid = threadIdx.x;
    const int w = tid >> 5, l = tid & 31;
    const int lg = l >> 2, lk = l & 3;
    const int wm = (w >> 2) * 64;       // 0,64
    const int wn = (w & 3) * 32;        // 0,32,64,96
    const int m0 = blockIdx.y * 128, n0 = blockIdx.x * 128;

    const uint32_t rAaddr = (uint32_t)__cvta_generic_to_shared(rA);
    const uint32_t rBaddr = (uint32_t)__cvta_generic_to_shared(rB);

    const int ac0 = tid, ac1 = tid + 256;            // A: 512 16B-chunks
    const int ar0 = ac0 >> 2, ao0 = (ac0 & 3) * 4;
    const int ar1 = ac1 >> 2, ao1 = (ac1 & 3) * 4;
    const int bc0 = tid, bc1 = tid + 256;            // B: 512 16B-chunks
    const int br0 = bc0 >> 5, bo0 = (bc0 & 31) * 4;
    const int br1 = bc1 >> 5, bo1 = (bc1 & 31) * 4;

    auto load_tile = [&](int kt, int buf) {
        uint32_t sa = rAaddr + buf * (128 * AST * 4);
        uint32_t sb = rBaddr + buf * (16 * BST * 4);
        cp16(sa + (ar0 * AST + ao0) * 4, A + (size_t)(m0 + ar0) * DMODEL + kt + ao0);
        cp16(sa + (ar1 * AST + ao1) * 4, A + (size_t)(m0 + ar1) * DMODEL + kt + ao1);
        cp16(sb + (br0 * BST + bo0) * 4, W + (size_t)(kt + br0) * DMODEL + n0 + bo0);
        cp16(sb + (br1 * BST + bo1) * 4, W + (size_t)(kt + br1) * DMODEL + n0 + bo1);
        cp_commit();
    };

    float c[4][4][4];
#pragma unroll
    for (int mi = 0; mi < 4; ++mi)
#pragma unroll
        for (int nj = 0; nj < 4; ++nj)
#pragma unroll
            for (int t = 0; t < 4; ++t) c[mi][nj][t] = 0.f;

    load_tile(0, 0);
    load_tile(16, 1);

    for (int it = 0; it < DMODEL / 16; ++it) {
        const float* cA = rA + (it & 1) * (128 * AST);
        const float* cB = rB + (it & 1) * (16 * BST);
        cp_wait<1>();          // raw tile landed
        __syncthreads();       // also: prev mma done reading packed arrays

        // ---- pre-split pass: raw fp32 -> packed bf16x2 hi/lo ----
#pragma unroll
        for (int i = 0; i < 4; ++i) {   // A: 1024 k-pairs (128 m x 8 kp)
            int p = tid + 256 * i;
            int m = p & 127, kp = p >> 7;
            float2 ap = *(const float2*)&cA[m * AST + 2 * kp];
            uint32_t hi = pack_bf16x2(ap.x, ap.y);
            float r0 = ap.x - __uint_as_float(hi << 16);
            float r1 = ap.y - __uint_as_float(hi & 0xffff0000u);
            AH[kp * PKS + m] = hi;
            AL[kp * PKS + m] = pack_bf16x2(r0, r1);
        }
#pragma unroll
        for (int i = 0; i < 4; ++i) {   // B: 1024 k-pairs (8 kp x 128 n)
            int p = tid + 256 * i;
            int n = p & 127, kp = p >> 7;
            float b0 = cB[(2 * kp) * BST + n];
            float b1 = cB[(2 * kp + 1) * BST + n];
            uint32_t hi = pack_bf16x2(b0, b1);
            float r0 = b0 - __uint_as_float(hi << 16);
            float r1 = b1 - __uint_as_float(hi & 0xffff0000u);
            BH[kp * PKS + n] = hi;
            BL[kp * PKS + n] = pack_bf16x2(r0, r1);
        }
        __syncthreads();       // packed arrays visible; raw tile consumed

        if (it + 2 < DMODEL / 16) load_tile((it + 2) * 16, it & 1);
        else cp_commit();      // keep group count in step

        // ---- mma loop: pure LDS + bf16 mma (one k16 step) ----
        uint32_t aH[4][4], aL[4][4];
#pragma unroll
        for (int mi = 0; mi < 4; ++mi) {
            int mb = wm + 16 * mi + lg;
            aH[mi][0] = AH[lk * PKS + mb];
            aH[mi][1] = AH[lk * PKS + mb + 8];
            aH[mi][2] = AH[(lk + 4) * PKS + mb];
            aH[mi][3] = AH[(lk + 4) * PKS + mb + 8];
            aL[mi][0] = AL[lk * PKS + mb];
            aL[mi][1] = AL[lk * PKS + mb + 8];
            aL[mi][2] = AL[(lk + 4) * PKS + mb];
            aL[mi][3] = AL[(lk + 4) * PKS + mb + 8];
        }
#pragma unroll
        for (int nj = 0; nj < 4; ++nj) {
            int nb = wn + 8 * nj + lg;
            uint32_t bH0 = BH[lk * PKS + nb], bH1 = BH[(lk + 4) * PKS + nb];
            uint32_t bL0 = BL[lk * PKS + nb], bL1 = BL[(lk + 4) * PKS + nb];
#pragma unroll
            for (int mi = 0; mi < 4; ++mi) {
                mma_bf16(c[mi][nj], aH[mi], bH0, bH1);
                mma_bf16(c[mi][nj], aH[mi], bL0, bL1);
                mma_bf16(c[mi][nj], aL[mi], bH0, bH1);
            }
        }
    }

    // epilogue: bias + store (optionally remapped to (B,H,N,DK))
#pragma unroll
    for (int mi = 0; mi < 4; ++mi) {
#pragma unroll
        for (int nj = 0; nj < 4; ++nj) {
            int col = n0 + wn + 8 * nj + 2 * lk;
            float b0 = __ldg(&bias[col]), b1 = __ldg(&bias[col + 1]);
#pragma unroll
            for (int half = 0; half < 2; ++half) {
                int m = m0 + wm + 16 * mi + lg + 8 * half;
                float2 v;
                v.x = c[mi][nj][2 * half + 0] + b0;
                v.y = c[mi][nj][2 * half + 1] + b1;
                size_t idx;
                if (SPLIT) {
                    int b = m >> 11, row = m & 2047;
                    int h = col >> 6, dk = col & 63;
                    idx = (((size_t)(b * NHEAD + h) * NSEQ + row) * DKH + dk);
                } else {
                    idx = (size_t)m * DMODEL + col;
                }
                *(float2*)&out[idx] = v;
            }
        }
    }
}

__global__ __launch_bounds__(256)
void proj_qkv_kernel(const float* __restrict__ q, const float* __restrict__ k,
                     const float* __restrict__ v,
                     const float* __restrict__ Wq, const float* __restrict__ Wk,
                     const float* __restrict__ Wv,
                     const float* __restrict__ bq, const float* __restrict__ bk,
                     const float* __restrict__ bv,
                     float* __restrict__ oq, float* __restrict__ ok,
                     float* __restrict__ ov) {
    const float *A, *W, *bias;
    float* out;
    if (blockIdx.z == 0)      { A = q; W = Wq; bias = bq; out = oq; }
    else if (blockIdx.z == 1) { A = k; W = Wk; bias = bk; out = ok; }
    else                      { A = v; W = Wv; bias = bv; out = ov; }
    proj_core<true>(A, W, bias, out);
}

__global__ __launch_bounds__(256)
void proj_out_kernel(const float* __restrict__ A, const float* __restrict__ W,
                     const float* __restrict__ bias, float* __restrict__ out) {
    proj_core<false>(A, W, bias, out);
}

// ---------------- fused masked flash attention (tf32 mma, fragment softmax) -
// (unchanged from R10 best: 128-query tile, 8 warps, warp owns 16 rows x 64
//  key cols; softmax in fragment view; 2 block barriers per key-tile)
#define QPAD 68
#define KPAD 72
__global__ __launch_bounds__(256)
void attn_kernel() {
    extern __shared__ char smraw[];
    uint32_t* Qs = (uint32_t*)smraw;                       // [128][QPAD] tf32
    float*    Ps = (float*)smraw;                          // aliases Qs
    uint32_t* Ks = (uint32_t*)(smraw + 128 * QPAD * 4);    // [d=64][key KPAD]
    uint32_t* Vs = (uint32_t*)(smraw + 128 * QPAD * 4 + 64 * KPAD * 4); // [key][dk KPAD]
    unsigned* Ms = (unsigned*)(smraw + 128 * QPAD * 4 + 2 * 64 * KPAD * 4); // [128][2]

    const int tid = threadIdx.x;
    const int w = tid >> 5, l = tid & 31;
    const int lg = l >> 2, lk = l & 3;
    const int rb = w * 16;              // warp row band (16 rows)
    const int bh = blockIdx.y;
    const int b = bh >> 4;
    const int h = bh & 15;
    const int q0 = blockIdx.x * 128;

    const float* Qg = g_Q + ((size_t)bh * NSEQ + q0) * DKH;
    const float* Kg = g_K + (size_t)bh * NSEQ * DKH;
    const float* Vg = g_V + (size_t)bh * NSEQ * DKH;

    // ---- load Q tile (tf32), q-major ----
#pragma unroll
    for (int i = 0; i < 8; ++i) {
        int v = tid + 256 * i;
        int row = v >> 4, d4 = (v & 15) * 4;
        float4 q = *(const float4*)(Qg + (size_t)row * DKH + d4);
        Qs[row * QPAD + d4 + 0] = f2tf32(q.x);
        Qs[row * QPAD + d4 + 1] = f2tf32(q.y);
        Qs[row * QPAD + d4 + 2] = f2tf32(q.z);
        Qs[row * QPAD + d4 + 3] = f2tf32(q.w);
    }
    __syncthreads();

    // preload Q fragments (rows rb..rb+15, all 8 k-steps); Qs dead afterwards
    uint32_t qf[8][4];
#pragma unroll
    for (int ks = 0; ks < 8; ++ks) {
        qf[ks][0] = Qs[(rb + lg) * QPAD + ks * 8 + lk];
        qf[ks][1] = Qs[(rb + lg + 8) * QPAD + ks * 8 + lk];
        qf[ks][2] = Qs[(rb + lg) * QPAD + ks * 8 + lk + 4];
        qf[ks][3] = Qs[(rb + lg + 8) * QPAD + ks * 8 + lk + 4];
    }

    // softmax state: thread owns rows rb+lg (idx 0) and rb+lg+8 (idx 1)
    float m_run[2] = {-1e30f, -1e30f};
    float l_run[2] = {0.f, 0.f};

    // PV accumulators: o[nj] rows (lg, lg+8) x cols (8nj+2lk, +1)
    float o[8][4];
#pragma unroll
    for (int nj = 0; nj < 8; ++nj)
#pragma unroll
        for (int t = 0; t < 4; ++t) o[nj][t] = 0.f;

    const int maskRowBase = b * NSEQ + q0;

    for (int kt = 0; kt < NSEQ / 64; ++kt) {
        __syncthreads();   // prior iteration done with Ks/Vs/Ms
        // ---- fill K (transposed [d][key]), V ([key][dk]), mask words ----
#pragma unroll
        for (int i = 0; i < 4; ++i) {
            int v = tid + 256 * i;
            {   // K
                int key = v & 63, d4 = (v >> 6) * 4;
                float4 kv = *(const float4*)(Kg + (size_t)(kt * 64 + key) * DKH + d4);
                Ks[(d4 + 0) * KPAD + key] = f2tf32(kv.x);
                Ks[(d4 + 1) * KPAD + key] = f2tf32(kv.y);
                Ks[(d4 + 2) * KPAD + key] = f2tf32(kv.z);
                Ks[(d4 + 3) * KPAD + key] = f2tf32(kv.w);
            }
            {   // V
                int key = v >> 4, d4 = (v & 15) * 4;
                float4 vv = *(const float4*)(Vg + (size_t)(kt * 64 + key) * DKH + d4);
                Vs[key * KPAD + d4 + 0] = f2tf32(vv.x);
                Vs[key * KPAD + d4 + 1] = f2tf32(vv.y);
                Vs[key * KPAD + d4 + 2] = f2tf32(vv.z);
                Vs[key * KPAD + d4 + 3] = f2tf32(vv.w);
            }
        }
        Ms[tid] = g_pmask[(size_t)(maskRowBase + (tid >> 1)) * (NSEQ / 32)
                          + kt * 2 + (tid & 1)];
        __syncthreads();

        // ---- S = Q @ K^T (mma, registers only) ----
        float sc[8][4];
#pragma unroll
        for (int nj = 0; nj < 8; ++nj)
#pragma unroll
            for (int t = 0; t < 4; ++t) sc[nj][t] = 0.f;
#pragma unroll
        for (int ks = 0; ks < 8; ++ks) {
#pragma unroll
            for (int nj = 0; nj < 8; ++nj) {
                int nb = 8 * nj + lg;
                uint32_t b0 = Ks[(ks * 8 + lk) * KPAD + nb];
                uint32_t b1 = Ks[(ks * 8 + lk + 4) * KPAD + nb];
                mma_tf32(sc[nj], qf[ks], b0, b1);
            }
        }

        // ---- fragment softmax (rows rb+lg, rb+lg+8) ----
#pragma unroll
        for (int r = 0; r < 2; ++r) {
            int row = rb + lg + 8 * r;
            unsigned mwA = Ms[row * 2], mwB = Ms[row * 2 + 1];
            int t0 = 2 * r;
            float rm = -1e30f;
#pragma unroll
            for (int nj = 0; nj < 8; ++nj) {
                int col = 8 * nj + 2 * lk;
                unsigned word = (nj < 4) ? mwA : mwB;
                float v0 = ((word >> (col & 31)) & 1u) ? sc[nj][t0] * 0.125f : NEGVAL;
                float v1 = ((word >> ((col + 1) & 31)) & 1u) ? sc[nj][t0 + 1] * 0.125f : NEGVAL;
                sc[nj][t0] = v0;
                sc[nj][t0 + 1] = v1;
                rm = fmaxf(rm, fmaxf(v0, v1));
            }
            rm = fmaxf(rm, __shfl_xor_sync(0xffffffffu, rm, 1));
            rm = fmaxf(rm, __shfl_xor_sync(0xffffffffu, rm, 2));
            float mn = fmaxf(m_run[r], rm);
            float corr = __expf(m_run[r] - mn);
            m_run[r] = mn;
            float ls = 0.f;
#pragma unroll
            for (int nj = 0; nj < 8; ++nj) {
                float p0 = __uint_as_float(f2tf32(__expf(sc[nj][t0] - mn)));
                float p1 = __uint_as_float(f2tf32(__expf(sc[nj][t0 + 1] - mn)));
                sc[nj][t0] = p0;
                sc[nj][t0 + 1] = p1;
                ls += p0 + p1;
            }
            ls += __shfl_xor_sync(0xffffffffu, ls, 1);
            ls += __shfl_xor_sync(0xffffffffu, ls, 2);
            l_run[r] = l_run[r] * corr + ls;
#pragma unroll
            for (int nj = 0; nj < 8; ++nj) {
                o[nj][t0] *= corr;
                o[nj][t0 + 1] *= corr;
            }
#pragma unroll
            for (int nj = 0; nj < 8; ++nj)
                *(float2*)&Ps[row * QPAD + 8 * nj + 2 * lk] =
                    make_float2(sc[nj][t0], sc[nj][t0 + 1]);
        }
        __syncwarp();

        // ---- O += P @ V (mma) ----
#pragma unroll
        for (int ks = 0; ks < 8; ++ks) {
            uint32_t af[4];
            af[0] = __float_as_uint(Ps[(rb + lg) * QPAD + ks * 8 + lk]);
            af[1] = __float_as_uint(Ps[(rb + lg + 8) * QPAD + ks * 8 + lk]);
            af[2] = __float_as_uint(Ps[(rb + lg) * QPAD + ks * 8 + lk + 4]);
            af[3] = __float_as_uint(Ps[(rb + lg + 8) * QPAD + ks * 8 + lk + 4]);
#pragma unroll
            for (int nj = 0; nj < 8; ++nj) {
                int nb = 8 * nj + lg;
                uint32_t b0 = Vs[(ks * 8 + lk) * KPAD + nb];
                uint32_t b1 = Vs[(ks * 8 + lk + 4) * KPAD + nb];
                mma_tf32(o[nj], af, b0, b1);
            }
        }
    }

    // ---- normalize and write context (B,N,D) ----
    float inv0 = 1.0f / l_run[0], inv1 = 1.0f / l_run[1];
    float* Cg = g_C + ((size_t)(b * NSEQ + q0)) * DMODEL + h * DKH;
#pragma unroll
    for (int nj = 0; nj < 8; ++nj) {
        int col = 8 * nj + 2 * lk;
        *(float2*)&Cg[(size_t)(rb + lg) * DMODEL + col] =
            make_float2(o[nj][0] * inv0, o[nj][1] * inv0);
        *(float2*)&Cg[(size_t)(rb + lg + 8) * DMODEL + col] =
            make_float2(o[nj][2] * inv1, o[nj][3] * inv1);
    }
}

// ---------------- launch ----------------------------------------------------
extern "C" void kernel_launch(void* const* d_in, const int* in_sizes, int n_in,
                              void* d_out, int out_size) {
    const float* query = (const float*)d_in[0];
    const float* key   = (const float*)d_in[1];
    const float* value = (const float*)d_in[2];
    const int*   mask  = (const int*)d_in[3];
    const float* Wq = (const float*)d_in[4];
    const float* bq = (const float*)d_in[5];
    const float* Wk = (const float*)d_in[6];
    const float* bk = (const float*)d_in[7];
    const float* Wv = (const float*)d_in[8];
    const float* bv = (const float*)d_in[9];
    const float* Wo = (const float*)d_in[10];
    const float* bo = (const float*)d_in[11];
    float* out = (float*)d_out;

    float *pQ, *pK, *pV, *pC;
    cudaGetSymbolAddress((void**)&pQ, g_Q);
    cudaGetSymbolAddress((void**)&pK, g_K);
    cudaGetSymbolAddress((void**)&pV, g_V);
    cudaGetSymbolAddress((void**)&pC, g_C);

    // 1) pack mask to bits
    pack_mask_kernel<<<(BATCH * NSEQ * NSEQ) / 256, 256>>>(mask);

    // 2) Q/K/V projections (3xBF16, cp.async pipelined), one merged launch
    cudaFuncSetAttribute(proj_qkv_kernel,
                         cudaFuncAttributeMaxDynamicSharedMemorySize, PROJ_SMEM);
    cudaFuncSetAttribute(proj_out_kernel,
                         cudaFuncAttributeMaxDynamicSharedMemorySize, PROJ_SMEM);
    dim3 gq(DMODEL / 128, MROWS / 128, 3);
    proj_qkv_kernel<<<gq, 256, PROJ_SMEM>>>(query, key, value, Wq, Wk, Wv,
                                            bq, bk, bv, pQ, pK, pV);

    // 3) fused masked attention (tf32 mma, fragment softmax)
    const int attn_smem = 128 * QPAD * 4 + 2 * 64 * KPAD * 4 + 128 * 2 * 4; // 72704
    cudaFuncSetAttribute(attn_kernel, cudaFuncAttributeMaxDynamicSharedMemorySize,
                         attn_smem);
    attn_kernel<<<dim3(NSEQ / 128, BATCH * NHEAD), 256, attn_smem>>>();

    // 4) output projection (3xBF16, cp.async pipelined) -> d_out
    dim3 go(DMODEL / 128, MROWS / 128);
    proj_out_kernel<<<go, 256, PROJ_SMEM>>>(pC, Wo, bo, out);
}

// round 12
// speedup vs baseline: 1.2093x; 1.2093x over previous
#include <cuda_runtime.h>
#include <cstdint>
#include <cstddef>

// Problem constants
#define BATCH  4
#define NSEQ   2048
#define DMODEL 1024
#define NHEAD  16
#define DKH    64
#define MROWS  (BATCH * NSEQ)   // 8192
#define NEGVAL (-1e11f)

// ---------------- scratch (device globals; no allocation allowed) ----------
__device__ float    g_Q[BATCH * NHEAD * NSEQ * DKH];   // (B,H,N,DK)
__device__ float    g_K[BATCH * NHEAD * NSEQ * DKH];
__device__ float    g_V[BATCH * NHEAD * NSEQ * DKH];
__device__ float    g_C[BATCH * NSEQ * DMODEL];        // attention context (B,N,D)
__device__ unsigned g_pmask[BATCH * NSEQ * NSEQ / 32]; // bit-packed mask

// ---------------- helpers ---------------------------------------------------
__device__ __forceinline__ uint32_t f2tf32(float x) {
    uint32_t r;
    asm("cvt.rna.tf32.f32 %0, %1;" : "=r"(r) : "f"(x));
    return r;
}

__device__ __forceinline__ void mma_tf32(float* c, const uint32_t* a,
                                         uint32_t b0, uint32_t b1) {
    asm volatile(
        "mma.sync.aligned.m16n8k8.row.col.f32.tf32.tf32.f32 "
        "{%0,%1,%2,%3}, {%4,%5,%6,%7}, {%8,%9}, {%0,%1,%2,%3};"
        : "+f"(c[0]), "+f"(c[1]), "+f"(c[2]), "+f"(c[3])
        : "r"(a[0]), "r"(a[1]), "r"(a[2]), "r"(a[3]), "r"(b0), "r"(b1));
}

__device__ __forceinline__ void cp16(uint32_t dst, const float* src) {
    asm volatile("cp.async.ca.shared.global [%0], [%1], 16;\n"
                 :: "r"(dst), "l"(src));
}
__device__ __forceinline__ void cp_commit() {
    asm volatile("cp.async.commit_group;\n");
}
template <int N>
__device__ __forceinline__ void cp_wait() {
    asm volatile("cp.async.wait_group %0;\n" :: "n"(N));
}

// ---------------- mask bit-pack: 67MB int32 -> 2MB bits --------------------
__global__ void pack_mask_kernel(const int* __restrict__ mask) {
    int idx = blockIdx.x * blockDim.x + threadIdx.x;
    unsigned bit = (mask[idx] != 0) ? 1u : 0u;
    unsigned w = __ballot_sync(0xffffffffu, bit);
    if ((threadIdx.x & 31) == 0) g_pmask[idx >> 5] = w;
}

// ---------------- projection GEMM core: 2xTF32 + cp.async pipeline ----------
// (reverted to R10-proven version: 243.9us, 118 regs, 2 CTA/SM)
#define AST 20    // A smem row stride (floats)
#define BST 136   // B smem row stride (floats)

template <bool SPLIT>
__device__ __forceinline__ void proj_core(const float* __restrict__ A,
                                          const float* __restrict__ W,
                                          const float* __restrict__ bias,
                                          float* __restrict__ out) {
    __shared__ float sA[2][128 * AST];   // [m][k] raw fp32
    __shared__ float sB[2][16 * BST];    // [k][n] raw fp32

    const int tid = threadIdx.x;
    const int w = tid >> 5, l = tid & 31;
    const int lg = l >> 2, lk = l & 3;
    const int wm = (w >> 2) * 64;       // 0,64
    const int wn = (w & 3) * 32;        // 0,32,64,96
    const int m0 = blockIdx.y * 128, n0 = blockIdx.x * 128;

    const uint32_t sAaddr0 = (uint32_t)__cvta_generic_to_shared(&sA[0][0]);
    const uint32_t sAaddr1 = (uint32_t)__cvta_generic_to_shared(&sA[1][0]);
    const uint32_t sBaddr0 = (uint32_t)__cvta_generic_to_shared(&sB[0][0]);
    const uint32_t sBaddr1 = (uint32_t)__cvta_generic_to_shared(&sB[1][0]);

    const int ac0 = tid, ac1 = tid + 256;
    const int ar0 = ac0 >> 2, ao0 = (ac0 & 3) * 4;
    const int ar1 = ac1 >> 2, ao1 = (ac1 & 3) * 4;
    const int bc0 = tid, bc1 = tid + 256;
    const int br0 = bc0 >> 5, bo0 = (bc0 & 31) * 4;
    const int br1 = bc1 >> 5, bo1 = (bc1 & 31) * 4;

    auto load_tile = [&](int kt, int buf) {
        uint32_t sa = buf ? sAaddr1 : sAaddr0;
        uint32_t sb = buf ? sBaddr1 : sBaddr0;
        cp16(sa + (ar0 * AST + ao0) * 4, A + (size_t)(m0 + ar0) * DMODEL + kt + ao0);
        cp16(sa + (ar1 * AST + ao1) * 4, A + (size_t)(m0 + ar1) * DMODEL + kt + ao1);
        cp16(sb + (br0 * BST + bo0) * 4, W + (size_t)(kt + br0) * DMODEL + n0 + bo0);
        cp16(sb + (br1 * BST + bo1) * 4, W + (size_t)(kt + br1) * DMODEL + n0 + bo1);
        cp_commit();
    };

    float c[4][4][4];
#pragma unroll
    for (int mi = 0; mi < 4; ++mi)
#pragma unroll
        for (int nj = 0; nj < 4; ++nj)
#pragma unroll
            for (int t = 0; t < 4; ++t) c[mi][nj][t] = 0.f;

    load_tile(0, 0);
    load_tile(16, 1);

    for (int it = 0; it < DMODEL / 16; ++it) {
        const float* cA = sA[it & 1];
        const float* cB = sB[it & 1];
        cp_wait<1>();
        __syncthreads();

#pragma unroll
        for (int ks = 0; ks < 16; ks += 8) {
            uint32_t aH[4][4];
#pragma unroll
            for (int mi = 0; mi < 4; ++mi) {
                int mbase = wm + 16 * mi + lg;
                aH[mi][0] = f2tf32(cA[mbase * AST + ks + lk]);
                aH[mi][1] = f2tf32(cA[(mbase + 8) * AST + ks + lk]);
                aH[mi][2] = f2tf32(cA[mbase * AST + ks + lk + 4]);
                aH[mi][3] = f2tf32(cA[(mbase + 8) * AST + ks + lk + 4]);
            }
#pragma unroll
            for (int nj = 0; nj < 4; ++nj) {
                int nb = wn + 8 * nj + lg;
                float b0r = cB[(ks + lk) * BST + nb];
                float b1r = cB[(ks + lk + 4) * BST + nb];
                uint32_t bH0 = f2tf32(b0r), bH1 = f2tf32(b1r);
                uint32_t bL0 = __float_as_uint(b0r - __uint_as_float(bH0));
                uint32_t bL1 = __float_as_uint(b1r - __uint_as_float(bH1));
#pragma unroll
                for (int mi = 0; mi < 4; ++mi) {
                    mma_tf32(c[mi][nj], aH[mi], bH0, bH1);
                    mma_tf32(c[mi][nj], aH[mi], bL0, bL1);
                }
            }
        }
        __syncthreads();
        if (it + 2 < DMODEL / 16) load_tile((it + 2) * 16, it & 1);
        else cp_commit();
    }

#pragma unroll
    for (int mi = 0; mi < 4; ++mi) {
#pragma unroll
        for (int nj = 0; nj < 4; ++nj) {
            int col = n0 + wn + 8 * nj + 2 * lk;
            float b0 = __ldg(&bias[col]), b1 = __ldg(&bias[col + 1]);
#pragma unroll
            for (int half = 0; half < 2; ++half) {
                int m = m0 + wm + 16 * mi + lg + 8 * half;
                float2 v;
                v.x = c[mi][nj][2 * half + 0] + b0;
                v.y = c[mi][nj][2 * half + 1] + b1;
                size_t idx;
                if (SPLIT) {
                    int b = m >> 11, row = m & 2047;
                    int h = col >> 6, dk = col & 63;
                    idx = (((size_t)(b * NHEAD + h) * NSEQ + row) * DKH + dk);
                } else {
                    idx = (size_t)m * DMODEL + col;
                }
                *(float2*)&out[idx] = v;
            }
        }
    }
}

__global__ __launch_bounds__(256)
void proj_qkv_kernel(const float* __restrict__ q, const float* __restrict__ k,
                     const float* __restrict__ v,
                     const float* __restrict__ Wq, const float* __restrict__ Wk,
                     const float* __restrict__ Wv,
                     const float* __restrict__ bq, const float* __restrict__ bk,
                     const float* __restrict__ bv,
                     float* __restrict__ oq, float* __restrict__ ok,
                     float* __restrict__ ov) {
    const float *A, *W, *bias;
    float* out;
    if (blockIdx.z == 0)      { A = q; W = Wq; bias = bq; out = oq; }
    else if (blockIdx.z == 1) { A = k; W = Wk; bias = bk; out = ok; }
    else                      { A = v; W = Wv; bias = bv; out = ov; }
    proj_core<true>(A, W, bias, out);
}

__global__ __launch_bounds__(256)
void proj_out_kernel(const float* __restrict__ A, const float* __restrict__ W,
                     const float* __restrict__ bias, float* __restrict__ out) {
    proj_core<false>(A, W, bias, out);
}

// ---------------- fused masked flash attention (tf32 mma, fragment softmax) -
// R12: K/V streamed via double-buffered cp.async (zero register cost).
// K lands NATURAL [key][KST=68]; S-mma B-fragments read it directly
// (banks 4lg+lk+8ks all distinct -> conflict-free). V lands directly in its
// padded [key][VST=72] layout. In-place f2tf32 convert pass per tile.
#define QPAD 68
#define KST  68
#define VST  72
#define ATTN_SMEM (128 * QPAD * 4 + 2 * 64 * KST * 4 + 2 * 64 * VST * 4 + 256 * 4)
__global__ __launch_bounds__(256)
void attn_kernel() {
    extern __shared__ char smraw[];
    uint32_t* Qs = (uint32_t*)smraw;                       // [128][QPAD] tf32
    float*    Ps = (float*)smraw;                          // aliases Qs (Q dead first)
    float*    Kb = (float*)(smraw + 128 * QPAD * 4);       // [2][64][KST]
    float*    Vb = (float*)(smraw + 128 * QPAD * 4 + 2 * 64 * KST * 4); // [2][64][VST]
    unsigned* Ms = (unsigned*)(smraw + 128 * QPAD * 4 + 2 * 64 * KST * 4
                               + 2 * 64 * VST * 4);        // [128][2]

    const int tid = threadIdx.x;
    const int w = tid >> 5, l = tid & 31;
    const int lg = l >> 2, lk = l & 3;
    const int rb = w * 16;              // warp row band (16 rows)
    const int bh = blockIdx.y;
    const int b = bh >> 4;
    const int h = bh & 15;
    const int q0 = blockIdx.x * 128;

    const float* Qg = g_Q + ((size_t)bh * NSEQ + q0) * DKH;
    const float* Kg = g_K + (size_t)bh * NSEQ * DKH;
    const float* Vg = g_V + (size_t)bh * NSEQ * DKH;

    const uint32_t KbAddr = (uint32_t)__cvta_generic_to_shared(Kb);
    const uint32_t VbAddr = (uint32_t)__cvta_generic_to_shared(Vb);

    // cp.async K/V tile loader: 8 x 16B chunks per thread (K 4, V 4)
    auto load_kv = [&](int kt, int buf) {
        const float* Ksrc = Kg + (size_t)kt * 64 * DKH;
        const float* Vsrc = Vg + (size_t)kt * 64 * DKH;
        uint32_t kbase = KbAddr + buf * (64 * KST * 4);
        uint32_t vbase = VbAddr + buf * (64 * VST * 4);
#pragma unroll
        for (int i = 0; i < 4; ++i) {
            int ck = tid + 256 * i;
            int row = ck >> 4, c4 = (ck & 15) * 4;
            cp16(kbase + (row * KST + c4) * 4, Ksrc + row * DKH + c4);
            cp16(vbase + (row * VST + c4) * 4, Vsrc + row * DKH + c4);
        }
        cp_commit();
    };

    // ---- load Q tile (tf32), q-major ----
#pragma unroll
    for (int i = 0; i < 8; ++i) {
        int v = tid + 256 * i;
        int row = v >> 4, d4 = (v & 15) * 4;
        float4 q = *(const float4*)(Qg + (size_t)row * DKH + d4);
        Qs[row * QPAD + d4 + 0] = f2tf32(q.x);
        Qs[row * QPAD + d4 + 1] = f2tf32(q.y);
        Qs[row * QPAD + d4 + 2] = f2tf32(q.z);
        Qs[row * QPAD + d4 + 3] = f2tf32(q.w);
    }
    __syncthreads();

    // prologue: two K/V tiles in flight while we preload qf
    load_kv(0, 0);
    load_kv(1, 1);

    // preload Q fragments (rows rb..rb+15, all 8 k-steps); Qs dead afterwards
    uint32_t qf[8][4];
#pragma unroll
    for (int ks = 0; ks < 8; ++ks) {
        qf[ks][0] = Qs[(rb + lg) * QPAD + ks * 8 + lk];
        qf[ks][1] = Qs[(rb + lg + 8) * QPAD + ks * 8 + lk];
        qf[ks][2] = Qs[(rb + lg) * QPAD + ks * 8 + lk + 4];
        qf[ks][3] = Qs[(rb + lg + 8) * QPAD + ks * 8 + lk + 4];
    }

    // softmax state: thread owns rows rb+lg (idx 0) and rb+lg+8 (idx 1)
    float m_run[2] = {-1e30f, -1e30f};
    float l_run[2] = {0.f, 0.f};

    // PV accumulators: o[nj] rows (lg, lg+8) x cols (8nj+2lk, +1)
    float o[8][4];
#pragma unroll
    for (int nj = 0; nj < 8; ++nj)
#pragma unroll
        for (int t = 0; t < 4; ++t) o[nj][t] = 0.f;

    const int maskRowBase = b * NSEQ + q0;

    for (int kt = 0; kt < NSEQ / 64; ++kt) {
        float* K0 = Kb + (kt & 1) * (64 * KST);
        float* V0 = Vb + (kt & 1) * (64 * VST);

        cp_wait<1>();       // this tile's raw K/V landed (own groups)
        __syncthreads();    // visible to all; prev iter fully done

        // ---- in-place tf32 convert (K 16 chunks + V 16 chunks per thread/8) ----
#pragma unroll
        for (int i = 0; i < 4; ++i) {
            int p = tid + 256 * i;
            int row = p >> 4, d4 = (p & 15) * 4;
            float4* ka = (float4*)&K0[row * KST + d4];
            float4 kv = *ka;
            uint4 kc = make_uint4(f2tf32(kv.x), f2tf32(kv.y), f2tf32(kv.z), f2tf32(kv.w));
            *(uint4*)ka = kc;
            float4* va = (float4*)&V0[row * VST + d4];
            float4 vv = *va;
            uint4 vc = make_uint4(f2tf32(vv.x), f2tf32(vv.y), f2tf32(vv.z), f2tf32(vv.w));
            *(uint4*)va = vc;
        }
        Ms[tid] = g_pmask[(size_t)(maskRowBase + (tid >> 1)) * (NSEQ / 32)
                          + kt * 2 + (tid & 1)];
        __syncthreads();

        // ---- S = Q @ K^T (mma; B-fragments from natural K) ----
        float sc[8][4];
#pragma unroll
        for (int nj = 0; nj < 8; ++nj)
#pragma unroll
            for (int t = 0; t < 4; ++t) sc[nj][t] = 0.f;
#pragma unroll
        for (int ks = 0; ks < 8; ++ks) {
#pragma unroll
            for (int nj = 0; nj < 8; ++nj) {
                int nb = 8 * nj + lg;
                uint32_t b0 = __float_as_uint(K0[nb * KST + ks * 8 + lk]);
                uint32_t b1 = __float_as_uint(K0[nb * KST + ks * 8 + lk + 4]);
                mma_tf32(sc[nj], qf[ks], b0, b1);
            }
        }

        // ---- fragment softmax (rows rb+lg, rb+lg+8) ----
#pragma unroll
        for (int r = 0; r < 2; ++r) {
            int row = rb + lg + 8 * r;
            unsigned mwA = Ms[row * 2], mwB = Ms[row * 2 + 1];
            int t0 = 2 * r;
            float rm = -1e30f;
#pragma unroll
            for (int nj = 0; nj < 8; ++nj) {
                int col = 8 * nj + 2 * lk;
                unsigned word = (nj < 4) ? mwA : mwB;
                float v0 = ((word >> (col & 31)) & 1u) ? sc[nj][t0] * 0.125f : NEGVAL;
                float v1 = ((word >> ((col + 1) & 31)) & 1u) ? sc[nj][t0 + 1] * 0.125f : NEGVAL;
                sc[nj][t0] = v0;
                sc[nj][t0 + 1] = v1;
                rm = fmaxf(rm, fmaxf(v0, v1));
            }
            rm = fmaxf(rm, __shfl_xor_sync(0xffffffffu, rm, 1));
            rm = fmaxf(rm, __shfl_xor_sync(0xffffffffu, rm, 2));
            float mn = fmaxf(m_run[r], rm);
            float corr = __expf(m_run[r] - mn);
            m_run[r] = mn;
            float ls = 0.f;
#pragma unroll
            for (int nj = 0; nj < 8; ++nj) {
                float p0 = __uint_as_float(f2tf32(__expf(sc[nj][t0] - mn)));
                float p1 = __uint_as_float(f2tf32(__expf(sc[nj][t0 + 1] - mn)));
                sc[nj][t0] = p0;
                sc[nj][t0 + 1] = p1;
                ls += p0 + p1;
            }
            ls += __shfl_xor_sync(0xffffffffu, ls, 1);
            ls += __shfl_xor_sync(0xffffffffu, ls, 2);
            l_run[r] = l_run[r] * corr + ls;
#pragma unroll
            for (int nj = 0; nj < 8; ++nj) {
                o[nj][t0] *= corr;
                o[nj][t0 + 1] *= corr;
            }
#pragma unroll
            for (int nj = 0; nj < 8; ++nj)
                *(float2*)&Ps[row * QPAD + 8 * nj + 2 * lk] =
                    make_float2(sc[nj][t0], sc[nj][t0 + 1]);
        }
        __syncwarp();

        // ---- O += P @ V (mma) ----
#pragma unroll
        for (int ks = 0; ks < 8; ++ks) {
            uint32_t af[4];
            af[0] = __float_as_uint(Ps[(rb + lg) * QPAD + ks * 8 + lk]);
            af[1] = __float_as_uint(Ps[(rb + lg + 8) * QPAD + ks * 8 + lk]);
            af[2] = __float_as_uint(Ps[(rb + lg) * QPAD + ks * 8 + lk + 4]);
            af[3] = __float_as_uint(Ps[(rb + lg + 8) * QPAD + ks * 8 + lk + 4]);
#pragma unroll
            for (int nj = 0; nj < 8; ++nj) {
                int nb = 8 * nj + lg;
                uint32_t b0 = __float_as_uint(V0[(ks * 8 + lk) * VST + nb]);
                uint32_t b1 = __float_as_uint(V0[(ks * 8 + lk + 4) * VST + nb]);
                mma_tf32(o[nj], af, b0, b1);
            }
        }

        __syncthreads();    // all warps done reading this K/V buffer
        if (kt + 2 < NSEQ / 64) load_kv(kt + 2, kt & 1);
        else cp_commit();   // keep group count in step
    }

    // ---- normalize and write context (B,N,D) ----
    float inv0 = 1.0f / l_run[0], inv1 = 1.0f / l_run[1];
    float* Cg = g_C + ((size_t)(b * NSEQ + q0)) * DMODEL + h * DKH;
#pragma unroll
    for (int nj = 0; nj < 8; ++nj) {
        int col = 8 * nj + 2 * lk;
        *(float2*)&Cg[(size_t)(rb + lg) * DMODEL + col] =
            make_float2(o[nj][0] * inv0, o[nj][1] * inv0);
        *(float2*)&Cg[(size_t)(rb + lg + 8) * DMODEL + col] =
            make_float2(o[nj][2] * inv1, o[nj][3] * inv1);
    }
}

// ---------------- launch ----------------------------------------------------
extern "C" void kernel_launch(void* const* d_in, const int* in_sizes, int n_in,
                              void* d_out, int out_size) {
    const float* query = (const float*)d_in[0];
    const float* key   = (const float*)d_in[1];
    const float* value = (const float*)d_in[2];
    const int*   mask  = (const int*)d_in[3];
    const float* Wq = (const float*)d_in[4];
    const float* bq = (const float*)d_in[5];
    const float* Wk = (const float*)d_in[6];
    const float* bk = (const float*)d_in[7];
    const float* Wv = (const float*)d_in[8];
    const float* bv = (const float*)d_in[9];
    const float* Wo = (const float*)d_in[10];
    const float* bo = (const float*)d_in[11];
    float* out = (float*)d_out;

    float *pQ, *pK, *pV, *pC;
    cudaGetSymbolAddress((void**)&pQ, g_Q);
    cudaGetSymbolAddress((void**)&pK, g_K);
    cudaGetSymbolAddress((void**)&pV, g_V);
    cudaGetSymbolAddress((void**)&pC, g_C);

    // 1) pack mask to bits
    pack_mask_kernel<<<(BATCH * NSEQ * NSEQ) / 256, 256>>>(mask);

    // 2) Q/K/V projections (2xTF32, cp.async pipelined), one merged launch
    dim3 gq(DMODEL / 128, MROWS / 128, 3);
    proj_qkv_kernel<<<gq, 256>>>(query, key, value, Wq, Wk, Wv,
                                 bq, bk, bv, pQ, pK, pV);

    // 3) fused masked attention (tf32 mma, fragment softmax, cp.async KV)
    cudaFuncSetAttribute(attn_kernel, cudaFuncAttributeMaxDynamicSharedMemorySize,
                         ATTN_SMEM);
    attn_kernel<<<dim3(NSEQ / 128, BATCH * NHEAD), 256, ATTN_SMEM>>>();

    // 4) output projection (2xTF32, cp.async pipelined) -> d_out
    dim3 go(DMODEL / 128, MROWS / 128);
    proj_out_kernel<<<go, 256>>>(pC, Wo, bo, out);
}